// round 11
// baseline (speedup 1.0000x reference)
#include <cuda_runtime.h>
#include <cuda_fp16.h>
#include <cstdint>

#define B_ 4
#define S_ 2048
#define D_ 1024
#define NT (B_*S_)
#define QS2    0.18033688011112042f   // 0.125 * log2(e)
#define SHIFT2 14.426950408889634f    // 10 * log2(e)
typedef uint32_t u32;

__device__ __half g_xh[(size_t)NT*D_], g_xl[(size_t)NT*D_];
__device__ __half g_qh[(size_t)NT*D_], g_ql[(size_t)NT*D_];
__device__ __half g_ah[(size_t)NT*D_], g_al[(size_t)NT*D_];
__device__ __half g_wqh[D_*D_], g_wql[D_*D_], g_woh[D_*D_], g_wol[D_*D_];

__device__ __forceinline__ u32 s2u(const void* p){u32 a;asm("{.reg .u64 t;cvta.to.shared.u64 t,%1;cvt.u32.u64 %0,t;}":"=r"(a):"l"(p));return a;}
__device__ __forceinline__ u32 swz(u32 r,u32 c16){return r*128u+((c16^(r&7u))<<4);}
__device__ __forceinline__ void spl(float v,__half&h,__half&l){h=__float2half_rn(v);l=__float2half_rn(v-__half2float(h));}
__device__ __forceinline__ u32 pkh(__half a,__half b){__half2 t=__halves2half2(a,b);return *(u32*)&t;}
__device__ __forceinline__ u32 pkf(float a,float b){__half2 t=__floats2half2_rn(a,b);return *(u32*)&t;}
__device__ __forceinline__ float ex2(float x){float r;asm("ex2.approx.f32 %0,%1;":"=f"(r):"f"(x));return r;}
__device__ __forceinline__ void ldsm4(u32* r,u32 a){asm volatile("ldmatrix.sync.aligned.m8n8.x4.shared.b16 {%0,%1,%2,%3},[%4];":"=r"(r[0]),"=r"(r[1]),"=r"(r[2]),"=r"(r[3]):"r"(a));}
__device__ __forceinline__ void ldsm4t(u32* r,u32 a){asm volatile("ldmatrix.sync.aligned.m8n8.x4.trans.shared.b16 {%0,%1,%2,%3},[%4];":"=r"(r[0]),"=r"(r[1]),"=r"(r[2]),"=r"(r[3]):"r"(a));}
__device__ __forceinline__ void mma16816(float* c,const u32* a,u32 b0,u32 b1){
  asm volatile("mma.sync.aligned.m16n8k16.row.col.f32.f16.f16.f32 {%0,%1,%2,%3},{%4,%5,%6,%7},{%8,%9},{%0,%1,%2,%3};"
    :"+f"(c[0]),"+f"(c[1]),"+f"(c[2]),"+f"(c[3])
    :"r"(a[0]),"r"(a[1]),"r"(a[2]),"r"(a[3]),"r"(b0),"r"(b1));}
__device__ __forceinline__ void cpa(u32 d,const void* s){asm volatile("cp.async.cg.shared.global [%0],[%1],16;"::"r"(d),"l"(s):"memory");}
#define CPC()  asm volatile("cp.async.commit_group;":::"memory")
#define CPW0() asm volatile("cp.async.wait_group 0;":::"memory")
#define CPW1() asm volatile("cp.async.wait_group 1;":::"memory")

// ---------------- fp32 -> fp16 hi/lo split ----------------
__global__ void split_k(const float* __restrict__ s,__half* __restrict__ dh,__half* __restrict__ dl,int n){
    int i=(blockIdx.x*blockDim.x+threadIdx.x)*4; if(i>=n) return;
    float4 v=*(const float4*)(s+i);
    __half h0,h1,h2,h3,l0,l1,l2,l3;
    spl(v.x,h0,l0);spl(v.y,h1,l1);spl(v.z,h2,l2);spl(v.w,h3,l3);
    *(uint2*)(dh+i)=make_uint2(pkh(h0,h1),pkh(h2,h3));
    *(uint2*)(dl+i)=make_uint2(pkh(l0,l1),pkh(l2,l3));
}

// ---------------- HMMA GEMM: C = A*W^T (+bias) ----------------
// CTA 128(M)x256(N), K-chunk 64, 256 thr = 8 warps (2x4), warp tile 64x64.
// cp.async double buffer, warp-staggered k16. THREE: AhWh+AhWl+AlWh. TWO: (Ah+Al)Wh.
template<bool THREE>
__global__ __launch_bounds__(256,1)
void gemm_mma(const __half* __restrict__ Ah,const __half* __restrict__ Al,
              const __half* __restrict__ Wh,const __half* __restrict__ Wl,
              const float* __restrict__ bias,
              __half* __restrict__ Ch,__half* __restrict__ Cl,float* __restrict__ Cf){
  extern __shared__ char smraw[];
  u32 sb=(s2u(smraw)+1023)&~1023u;
  const int tid=threadIdx.x,t=tid&31,w=tid>>5;
  const int bm=blockIdx.y*128,bn=blockIdx.x*256;
  const int wm=(w>>2)*64,wn=(w&3)*64;
  const u32 BUFSZ=THREE?98304u:65536u;   // Ah16K+Al16K+Wh32K(+Wl32K)
  float acc[4][8][4];
  #pragma unroll
  for(int a=0;a<4;a++)for(int j=0;j<8;j++)for(int e=0;e<4;e++)acc[a][j][e]=0.f;
  const __half* gA0=Ah+(size_t)bm*D_;
  const __half* gA1=Al+(size_t)bm*D_;
  const __half* gW0=Wh+(size_t)bn*D_;
  const __half* gW1=THREE?(Wl+(size_t)bn*D_):gW0;

  #pragma unroll
  for(int j=0;j<4;j++){int it=tid+256*j;u32 r=(u32)(it>>3),c=(u32)(it&7);
    cpa(sb+swz(r,c),gA0+(size_t)r*D_+c*8);
    cpa(sb+16384u+swz(r,c),gA1+(size_t)r*D_+c*8);}
  #pragma unroll
  for(int j=0;j<8;j++){int it=tid+256*j;u32 r=(u32)(it>>3),c=(u32)(it&7);
    cpa(sb+32768u+swz(r,c),gW0+(size_t)r*D_+c*8);
    if(THREE) cpa(sb+65536u+swz(r,c),gW1+(size_t)r*D_+c*8);}
  CPC();

  #pragma unroll 1
  for(int kc=0;kc<16;kc++){
    __syncthreads();
    if(kc<15){
      u32 bufb=sb+(u32)((kc+1)&1)*BUFSZ; int k0=(kc+1)*64;
      #pragma unroll
      for(int j=0;j<4;j++){int it=tid+256*j;u32 r=(u32)(it>>3),c=(u32)(it&7);
        cpa(bufb+swz(r,c),gA0+(size_t)r*D_+k0+c*8);
        cpa(bufb+16384u+swz(r,c),gA1+(size_t)r*D_+k0+c*8);}
      #pragma unroll
      for(int j=0;j<8;j++){int it=tid+256*j;u32 r=(u32)(it>>3),c=(u32)(it&7);
        cpa(bufb+32768u+swz(r,c),gW0+(size_t)r*D_+k0+c*8);
        if(THREE) cpa(bufb+65536u+swz(r,c),gW1+(size_t)r*D_+k0+c*8);}
      CPC(); CPW1();
    } else CPW0();
    __syncthreads();
    u32 ba=sb+(u32)(kc&1)*BUFSZ;
    #pragma unroll
    for(int kx=0;kx<4;kx++){
      int k16=(kx+(w&3))&3;               // warp-staggered K order
      u32 rA=(u32)(wm+(t&7)+((t>>3)&1)*8);
      u32 cA=(u32)(k16*2+(t>>4));
      u32 aH[4][4],aL[4][4];
      #pragma unroll
      for(int mt=0;mt<4;mt++){
        ldsm4(aH[mt],ba+swz(rA+(u32)mt*16u,cA));
        ldsm4(aL[mt],ba+16384u+swz(rA+(u32)mt*16u,cA));
      }
      u32 rB=(u32)(wn+(t&7)+((t>>4)<<3));
      u32 cB=(u32)(k16*2+((t>>3)&1));
      #pragma unroll
      for(int nn=0;nn<4;nn++){
        u32 bh[4],bl[4];
        ldsm4(bh,ba+32768u+swz(rB+(u32)nn*16u,cB));
        if(THREE) ldsm4(bl,ba+65536u+swz(rB+(u32)nn*16u,cB));
        #pragma unroll
        for(int mt=0;mt<4;mt++){
          mma16816(acc[mt][2*nn],aH[mt],bh[0],bh[1]);
          mma16816(acc[mt][2*nn+1],aH[mt],bh[2],bh[3]);
        }
        if(THREE){
          #pragma unroll
          for(int mt=0;mt<4;mt++){
            mma16816(acc[mt][2*nn],aH[mt],bl[0],bl[1]);
            mma16816(acc[mt][2*nn+1],aH[mt],bl[2],bl[3]);
          }
        }
        #pragma unroll
        for(int mt=0;mt<4;mt++){
          mma16816(acc[mt][2*nn],aL[mt],bh[0],bh[1]);
          mma16816(acc[mt][2*nn+1],aL[mt],bh[2],bh[3]);
        }
      }
    }
  }
  #pragma unroll
  for(int mt=0;mt<4;mt++){
    int R0=bm+wm+mt*16+(t>>2);
    #pragma unroll
    for(int j=0;j<8;j++){
      int col=bn+wn+j*8+(t&3)*2;
      float c0=acc[mt][j][0],c1=acc[mt][j][1],c2=acc[mt][j][2],c3=acc[mt][j][3];
      if(Cf){
        float b0=bias[col],b1=bias[col+1];
        float2 v0; v0.x=c0+b0; v0.y=c1+b1;
        float2 v1; v1.x=c2+b0; v1.y=c3+b1;
        *(float2*)(Cf+(size_t)R0*D_+col)=v0;
        *(float2*)(Cf+(size_t)(R0+8)*D_+col)=v1;
      }else{
        __half h0,l0,h1,l1;
        spl(c0,h0,l0);spl(c1,h1,l1);
        *(u32*)(Ch+(size_t)R0*D_+col)=pkh(h0,h1);
        *(u32*)(Cl+(size_t)R0*D_+col)=pkh(l0,l1);
        spl(c2,h0,l0);spl(c3,h1,l1);
        *(u32*)(Ch+(size_t)(R0+8)*D_+col)=pkh(h0,h1);
        *(u32*)(Cl+(size_t)(R0+8)*D_+col)=pkh(l0,l1);
      }
    }
  }
}

// ---------------- HMMA attention (q=k=v), fixed-shift softmax, exact diag ----
// CTA: 64 q-rows, 128 thr, occ 3. QK = Qh*Kh + exact fp32 diag; PV = P*Vh.
// Each 128-key tile processed in two 64-key halves to cut s/pl registers and
// interleave MUFU(exp) with TENSOR at 2x frequency.
__global__ __launch_bounds__(128,3)
void attn_mma(const __half* __restrict__ qh,const __half* __restrict__ ql,
              __half* __restrict__ oh,__half* __restrict__ ol){
  extern __shared__ char smraw[];
  u32 sb=(s2u(smraw)+1023)&~1023u;
  const int tid=threadIdx.x,t=tid&31,w=tid>>5;
  const int mi=w>>1,ni=w&1;
  const int qt=blockIdx.x,hb=blockIdx.y,b=hb>>4,h=hb&15;
  const size_t base=(size_t)b*S_*D_+(size_t)h*64;
  const int q0=qt*64;
  const int dkt=qt>>1;                 // kt tile containing the diagonal
  const int off=(qt&1)*64;             // q-row offset within that tile
  const u32 LD=sb+8192;                // exact diag values [64] f32
  const u32 KB=sb+9216;                // K tiles (2 x 16KB double buffer)
  float* Ldp=(float*)(smraw+(LD-s2u(smraw)));
  // Q: combine h+l in fp32, scale by QS2, store HI half only (K-major SW)
  {
    const __half* gqh=qh+base+(size_t)q0*D_;
    const __half* gql=ql+base+(size_t)q0*D_;
    #pragma unroll
    for(int j=0;j<4;j++){int it=tid+128*j;u32 r=(u32)(it>>3),c=(u32)(it&7);
      uint4 vh4=*(const uint4*)(gqh+(size_t)r*D_+c*8);
      uint4 vl4=*(const uint4*)(gql+(size_t)r*D_+c*8);
      const __half* hv=(const __half*)&vh4; const __half* lv=(const __half*)&vl4;
      u32 wh[4];
      #pragma unroll
      for(int e=0;e<4;e++){
        float a0=(__half2float(hv[2*e])+__half2float(lv[2*e]))*QS2;
        float a1=(__half2float(hv[2*e+1])+__half2float(lv[2*e+1]))*QS2;
        wh[e]=pkf(a0,a1);
      }
      u32 d0=sb+swz(r,c);
      asm volatile("st.shared.v4.b32 [%0],{%1,%2,%3,%4};"::"r"(d0),"r"(wh[0]),"r"(wh[1]),"r"(wh[2]),"r"(wh[3]):"memory");
    }
  }
  // Exact diagonal: row=tid>>1, each half-thread sums 32 dims of (qh+ql)^2
  {
    int r=tid>>1, hf=tid&1;
    const __half* ph=qh+base+(size_t)(q0+r)*D_+hf*32;
    const __half* pl2=ql+base+(size_t)(q0+r)*D_+hf*32;
    float acc2=0.f;
    #pragma unroll
    for(int c=0;c<4;c++){
      uint4 vh4=*(const uint4*)(ph+c*8);
      uint4 vl4=*(const uint4*)(pl2+c*8);
      const __half* hv=(const __half*)&vh4; const __half* lv=(const __half*)&vl4;
      #pragma unroll
      for(int e=0;e<8;e++){
        float v=__half2float(hv[e])+__half2float(lv[e]);
        acc2+=v*v;
      }
    }
    acc2+=__shfl_xor_sync(0xffffffffu,acc2,1);
    if(hf==0) Ldp[r]=acc2*QS2;
  }
  // prefetch K tile 0 (hi half only)
  {
    const __half* gpk=qh+base;
    #pragma unroll
    for(int j=0;j<8;j++){int it=tid+128*j;u32 r=(u32)(it>>3),c=(u32)(it&7);
      cpa(KB+swz(r,c),gpk+(size_t)r*D_+c*8);}
  }
  CPC();
  float o[2][8][4]; float ls[4]={0.f,0.f,0.f,0.f};
  #pragma unroll
  for(int a=0;a<2;a++)for(int j=0;j<8;j++)for(int e=0;e<4;e++)o[a][j][e]=0.f;
  #pragma unroll 1
  for(int kt=0;kt<16;kt++){
    __syncthreads();
    if(kt<15){
      u32 st=(u32)((kt+1)&1);
      const __half* gpk=qh+base+(size_t)((kt+1)*128)*D_;
      #pragma unroll
      for(int j=0;j<8;j++){int it=tid+128*j;u32 r=(u32)(it>>3),c=(u32)(it&7);
        cpa(KB+st*16384+swz(r,c),gpk+(size_t)r*D_+c*8);}
      CPC(); CPW1();
    } else CPW0();
    __syncthreads();
    u32 kb=KB+(u32)(kt&1)*16384;
    u32 rA=(u32)(mi*32+(t&7)+((t>>3)&1)*8);
    #pragma unroll
    for(int kh=0;kh<2;kh++){
      // ---- QK for this 64-key half ----
      float s[2][4][4];
      #pragma unroll
      for(int a=0;a<2;a++)for(int j=0;j<4;j++)for(int e=0;e<4;e++)s[a][j][e]=0.f;
      u32 rBb=(u32)(ni*64+kh*32+(t&7)+((t>>4)<<3));
      #pragma unroll
      for(int k16=0;k16<4;k16++){
        u32 qf[2][4];
        u32 cA=(u32)(k16*2+(t>>4));
        ldsm4(qf[0],sb+swz(rA,cA));
        ldsm4(qf[1],sb+swz(rA+16,cA));
        u32 cB=(u32)(k16*2+((t>>3)&1));
        u32 bh[2][4];
        ldsm4(bh[0],kb+swz(rBb,cB));
        ldsm4(bh[1],kb+swz(rBb+16,cB));
        #pragma unroll
        for(int jj=0;jj<2;jj++)
          #pragma unroll
          for(int mt=0;mt<2;mt++){
            mma16816(s[mt][2*jj],qf[mt],bh[jj][0],bh[jj][1]);
            mma16816(s[mt][2*jj+1],qf[mt],bh[jj][2],bh[jj][3]);
          }
      }
      // exact diagonal patch (one kt per CTA)
      if(kt==dkt){
        #pragma unroll
        for(int mt=0;mt<2;mt++)
          #pragma unroll
          for(int j=0;j<4;j++)
            #pragma unroll
            for(int e=0;e<4;e++){
              int rl=mi*32+mt*16+(t>>2)+((e>>1)<<3);
              int cl=ni*64+kh*32+j*8+(t&3)*2+(e&1);
              if(rl+off==cl) s[mt][j][e]=Ldp[rl];
            }
      }
      // ---- softmax (fixed shift) ----
      u32 pl[2][4][2];
      #pragma unroll
      for(int mt=0;mt<2;mt++)
        #pragma unroll
        for(int j=0;j<4;j++){
          float p0=ex2(s[mt][j][0]-SHIFT2),p1=ex2(s[mt][j][1]-SHIFT2);
          float p2=ex2(s[mt][j][2]-SHIFT2),p3=ex2(s[mt][j][3]-SHIFT2);
          ls[mt*2]+=p0+p1; ls[mt*2+1]+=p2+p3;
          pl[mt][j][0]=pkf(p0,p1); pl[mt][j][1]=pkf(p2,p3);
        }
      // ---- PV for this half ----
      u32 rV0=(u32)(ni*64+kh*32+(t&7)+((t>>3)&1)*8);
      #pragma unroll
      for(int kc=0;kc<2;kc++){
        u32 rV=rV0+(u32)kc*16u;
        u32 af[2][4];
        #pragma unroll
        for(int mt=0;mt<2;mt++){
          af[mt][0]=pl[mt][2*kc][0]; af[mt][1]=pl[mt][2*kc][1];
          af[mt][2]=pl[mt][2*kc+1][0]; af[mt][3]=pl[mt][2*kc+1][1];
        }
        #pragma unroll
        for(int nn=0;nn<4;nn++){
          u32 cV=(u32)(nn*2+(t>>4));
          u32 vh[4];
          ldsm4t(vh,kb+swz(rV,cV));
          #pragma unroll
          for(int mt=0;mt<2;mt++){
            mma16816(o[mt][2*nn],af[mt],vh[0],vh[1]);
            mma16816(o[mt][2*nn+1],af[mt],vh[2],vh[3]);
          }
        }
      }
    }
  }
  __syncthreads();
  #pragma unroll
  for(int e=0;e<4;e++){
    ls[e]+=__shfl_xor_sync(0xffffffffu,ls[e],1);
    ls[e]+=__shfl_xor_sync(0xffffffffu,ls[e],2);
  }
  u32 Osm=KB, Lsm=sb;
  if(ni==1){
    #pragma unroll
    for(int mt=0;mt<2;mt++){
      int r0=mi*32+mt*16+(t>>2);
      #pragma unroll
      for(int j=0;j<8;j++){
        int c=j*8+(t&3)*2;
        asm volatile("st.shared.v2.f32 [%0],{%1,%2};"::"r"(Osm+(u32)((r0*64+c)*4)),"f"(o[mt][j][0]),"f"(o[mt][j][1]):"memory");
        asm volatile("st.shared.v2.f32 [%0],{%1,%2};"::"r"(Osm+(u32)(((r0+8)*64+c)*4)),"f"(o[mt][j][2]),"f"(o[mt][j][3]):"memory");
      }
      if((t&3)==0){
        asm volatile("st.shared.f32 [%0],%1;"::"r"(Lsm+(u32)(r0*4)),"f"(ls[mt*2]):"memory");
        asm volatile("st.shared.f32 [%0],%1;"::"r"(Lsm+(u32)((r0+8)*4)),"f"(ls[mt*2+1]):"memory");
      }
    }
  }
  __syncthreads();
  if(ni==0){
    #pragma unroll
    for(int mt=0;mt<2;mt++){
      int rloc=mi*32+mt*16+(t>>2);
      float lA,lB;
      asm volatile("ld.shared.f32 %0,[%1];":"=f"(lA):"r"(Lsm+(u32)(rloc*4)));
      asm volatile("ld.shared.f32 %0,[%1];":"=f"(lB):"r"(Lsm+(u32)((rloc+8)*4)));
      float iA=1.f/(ls[mt*2]+lA), iB=1.f/(ls[mt*2+1]+lB);
      size_t R0=base+(size_t)(q0+rloc)*D_;
      size_t R1=base+(size_t)(q0+rloc+8)*D_;
      #pragma unroll
      for(int j=0;j<8;j++){
        int c=j*8+(t&3)*2;
        float a0,a1,b0f,b1f;
        asm volatile("ld.shared.v2.f32 {%0,%1},[%2];":"=f"(a0),"=f"(a1):"r"(Osm+(u32)((rloc*64+c)*4)));
        asm volatile("ld.shared.v2.f32 {%0,%1},[%2];":"=f"(b0f),"=f"(b1f):"r"(Osm+(u32)(((rloc+8)*64+c)*4)));
        float v0=(o[mt][j][0]+a0)*iA, v1=(o[mt][j][1]+a1)*iA;
        float v2=(o[mt][j][2]+b0f)*iB, v3=(o[mt][j][3]+b1f)*iB;
        __half h0,l0,h1,l1;
        spl(v0,h0,l0);spl(v1,h1,l1);
        *(u32*)(oh+R0+c)=pkh(h0,h1); *(u32*)(ol+R0+c)=pkh(l0,l1);
        spl(v2,h0,l0);spl(v3,h1,l1);
        *(u32*)(oh+R1+c)=pkh(h0,h1); *(u32*)(ol+R1+c)=pkh(l0,l1);
      }
    }
  }
}

// ---------------------------------------------------------------------------
extern "C" void kernel_launch(void* const* d_in, const int* in_sizes, int n_in,
                              void* d_out, int out_size) {
    const float* x=(const float*)d_in[0];
    const float* w_qkv=(const float*)d_in[1];
    const float* w_out=(const float*)d_in[2];
    const float* b_out=(const float*)d_in[3];
    float* out=(float*)d_out;

    __half *xh,*xl,*qh,*ql,*ah,*al,*wqh,*wql,*woh,*wol;
    cudaGetSymbolAddress((void**)&xh,g_xh);   cudaGetSymbolAddress((void**)&xl,g_xl);
    cudaGetSymbolAddress((void**)&qh,g_qh);   cudaGetSymbolAddress((void**)&ql,g_ql);
    cudaGetSymbolAddress((void**)&ah,g_ah);   cudaGetSymbolAddress((void**)&al,g_al);
    cudaGetSymbolAddress((void**)&wqh,g_wqh); cudaGetSymbolAddress((void**)&wql,g_wql);
    cudaGetSymbolAddress((void**)&woh,g_woh); cudaGetSymbolAddress((void**)&wol,g_wol);

    const int SMG3=196608+1024, SMG2=131072+1024, SMA=9216+32768+1024;
    cudaFuncSetAttribute(gemm_mma<true>,  cudaFuncAttributeMaxDynamicSharedMemorySize, SMG3);
    cudaFuncSetAttribute(gemm_mma<false>, cudaFuncAttributeMaxDynamicSharedMemorySize, SMG2);
    cudaFuncSetAttribute(attn_mma, cudaFuncAttributeMaxDynamicSharedMemorySize, SMA);

    split_k<<<(NT*D_)/1024,256>>>(x,xh,xl,NT*D_);
    split_k<<<(D_*D_)/1024,256>>>(w_qkv,wqh,wql,D_*D_);
    split_k<<<(D_*D_)/1024,256>>>(w_out,woh,wol,D_*D_);

    dim3 g1(D_/256, NT/128);             // (4, 64) = 256 CTAs
    gemm_mma<true><<<g1,256,SMG3>>>(xh,xl,wqh,wql,nullptr,qh,ql,nullptr);

    dim3 g2(S_/64, 64);                  // (32, 64)
    attn_mma<<<g2,128,SMA>>>(qh,ql,ah,al);

    gemm_mma<false><<<g1,256,SMG2>>>(ah,al,woh,nullptr,b_out,nullptr,nullptr,out);
}

// round 13
// speedup vs baseline: 1.0055x; 1.0055x over previous
#include <cuda_runtime.h>
#include <cuda_fp16.h>
#include <cstdint>

#define B_ 4
#define S_ 2048
#define D_ 1024
#define NT (B_*S_)
#define QS2    0.18033688011112042f   // 0.125 * log2(e)
#define SHIFT2 14.426950408889634f    // 10 * log2(e)
typedef uint32_t u32;

__device__ __half g_xh[(size_t)NT*D_], g_xl[(size_t)NT*D_];
__device__ __half g_qh[(size_t)NT*D_], g_ql[(size_t)NT*D_];
__device__ __half g_ah[(size_t)NT*D_], g_al[(size_t)NT*D_];
__device__ __half g_wqh[D_*D_], g_wql[D_*D_], g_woh[D_*D_], g_wol[D_*D_];

__device__ __forceinline__ u32 s2u(const void* p){u32 a;asm("{.reg .u64 t;cvta.to.shared.u64 t,%1;cvt.u32.u64 %0,t;}":"=r"(a):"l"(p));return a;}
__device__ __forceinline__ u32 swz(u32 r,u32 c16){return r*128u+((c16^(r&7u))<<4);}
__device__ __forceinline__ void spl(float v,__half&h,__half&l){h=__float2half_rn(v);l=__float2half_rn(v-__half2float(h));}
__device__ __forceinline__ u32 pkh(__half a,__half b){__half2 t=__halves2half2(a,b);return *(u32*)&t;}
__device__ __forceinline__ u32 pkf(float a,float b){__half2 t=__floats2half2_rn(a,b);return *(u32*)&t;}
__device__ __forceinline__ float ex2(float x){float r;asm("ex2.approx.f32 %0,%1;":"=f"(r):"f"(x));return r;}
__device__ __forceinline__ void ldsm4(u32* r,u32 a){asm volatile("ldmatrix.sync.aligned.m8n8.x4.shared.b16 {%0,%1,%2,%3},[%4];":"=r"(r[0]),"=r"(r[1]),"=r"(r[2]),"=r"(r[3]):"r"(a));}
__device__ __forceinline__ void ldsm4t(u32* r,u32 a){asm volatile("ldmatrix.sync.aligned.m8n8.x4.trans.shared.b16 {%0,%1,%2,%3},[%4];":"=r"(r[0]),"=r"(r[1]),"=r"(r[2]),"=r"(r[3]):"r"(a));}
__device__ __forceinline__ void mma16816(float* c,const u32* a,u32 b0,u32 b1){
  asm volatile("mma.sync.aligned.m16n8k16.row.col.f32.f16.f16.f32 {%0,%1,%2,%3},{%4,%5,%6,%7},{%8,%9},{%0,%1,%2,%3};"
    :"+f"(c[0]),"+f"(c[1]),"+f"(c[2]),"+f"(c[3])
    :"r"(a[0]),"r"(a[1]),"r"(a[2]),"r"(a[3]),"r"(b0),"r"(b1));}
__device__ __forceinline__ void cpa(u32 d,const void* s){asm volatile("cp.async.cg.shared.global [%0],[%1],16;"::"r"(d),"l"(s):"memory");}
#define CPC()  asm volatile("cp.async.commit_group;":::"memory")
#define CPW0() asm volatile("cp.async.wait_group 0;":::"memory")
#define CPW1() asm volatile("cp.async.wait_group 1;":::"memory")

// ---------------- fp32 -> fp16 hi/lo split ----------------
__global__ void split_k(const float* __restrict__ s,__half* __restrict__ dh,__half* __restrict__ dl,int n){
    int i=(blockIdx.x*blockDim.x+threadIdx.x)*4; if(i>=n) return;
    float4 v=*(const float4*)(s+i);
    __half h0,h1,h2,h3,l0,l1,l2,l3;
    spl(v.x,h0,l0);spl(v.y,h1,l1);spl(v.z,h2,l2);spl(v.w,h3,l3);
    *(uint2*)(dh+i)=make_uint2(pkh(h0,h1),pkh(h2,h3));
    *(uint2*)(dl+i)=make_uint2(pkh(l0,l1),pkh(l2,l3));
}

// ---------------- HMMA GEMM: C = A*W^T (+bias) ----------------
// CTA 128(M)x256(N), K-chunk 64, 256 thr = 8 warps (2x4), warp tile 64x64.
// cp.async double buffer, warp-staggered k16. B fragments preloaded per k16,
// A fragments loaded per-mt (8 live regs) to avoid spills.
// THREE: AhWh+AhWl+AlWh. TWO: (Ah+Al)Wh.
template<bool THREE>
__global__ __launch_bounds__(256,1)
void gemm_mma(const __half* __restrict__ Ah,const __half* __restrict__ Al,
              const __half* __restrict__ Wh,const __half* __restrict__ Wl,
              const float* __restrict__ bias,
              __half* __restrict__ Ch,__half* __restrict__ Cl,float* __restrict__ Cf){
  extern __shared__ char smraw[];
  u32 sb=(s2u(smraw)+1023)&~1023u;
  const int tid=threadIdx.x,t=tid&31,w=tid>>5;
  const int bm=blockIdx.y*128,bn=blockIdx.x*256;
  const int wm=(w>>2)*64,wn=(w&3)*64;
  const u32 BUFSZ=THREE?98304u:65536u;   // Ah16K+Al16K+Wh32K(+Wl32K)
  float acc[4][8][4];
  #pragma unroll
  for(int a=0;a<4;a++)for(int j=0;j<8;j++)for(int e=0;e<4;e++)acc[a][j][e]=0.f;
  const __half* gA0=Ah+(size_t)bm*D_;
  const __half* gA1=Al+(size_t)bm*D_;
  const __half* gW0=Wh+(size_t)bn*D_;
  const __half* gW1=THREE?(Wl+(size_t)bn*D_):gW0;

  #pragma unroll
  for(int j=0;j<4;j++){int it=tid+256*j;u32 r=(u32)(it>>3),c=(u32)(it&7);
    cpa(sb+swz(r,c),gA0+(size_t)r*D_+c*8);
    cpa(sb+16384u+swz(r,c),gA1+(size_t)r*D_+c*8);}
  #pragma unroll
  for(int j=0;j<8;j++){int it=tid+256*j;u32 r=(u32)(it>>3),c=(u32)(it&7);
    cpa(sb+32768u+swz(r,c),gW0+(size_t)r*D_+c*8);
    if(THREE) cpa(sb+65536u+swz(r,c),gW1+(size_t)r*D_+c*8);}
  CPC();

  #pragma unroll 1
  for(int kc=0;kc<16;kc++){
    __syncthreads();
    if(kc<15){
      u32 bufb=sb+(u32)((kc+1)&1)*BUFSZ; int k0=(kc+1)*64;
      #pragma unroll
      for(int j=0;j<4;j++){int it=tid+256*j;u32 r=(u32)(it>>3),c=(u32)(it&7);
        cpa(bufb+swz(r,c),gA0+(size_t)r*D_+k0+c*8);
        cpa(bufb+16384u+swz(r,c),gA1+(size_t)r*D_+k0+c*8);}
      #pragma unroll
      for(int j=0;j<8;j++){int it=tid+256*j;u32 r=(u32)(it>>3),c=(u32)(it&7);
        cpa(bufb+32768u+swz(r,c),gW0+(size_t)r*D_+k0+c*8);
        if(THREE) cpa(bufb+65536u+swz(r,c),gW1+(size_t)r*D_+k0+c*8);}
      CPC(); CPW1();
    } else CPW0();
    __syncthreads();
    u32 ba=sb+(u32)(kc&1)*BUFSZ;
    #pragma unroll
    for(int kx=0;kx<4;kx++){
      int k16=(kx+(w&3))&3;               // warp-staggered K order
      u32 rA=(u32)(wm+(t&7)+((t>>3)&1)*8);
      u32 cA=(u32)(k16*2+(t>>4));
      u32 rB=(u32)(wn+(t&7)+((t>>4)<<3));
      u32 cB=(u32)(k16*2+((t>>3)&1));
      // preload all B fragments for this k16
      u32 bh[4][4],bl[4][4];
      #pragma unroll
      for(int nn=0;nn<4;nn++){
        ldsm4(bh[nn],ba+32768u+swz(rB+(u32)nn*16u,cB));
        if(THREE) ldsm4(bl[nn],ba+65536u+swz(rB+(u32)nn*16u,cB));
      }
      // mt-outer: only 8 A regs live at a time
      #pragma unroll
      for(int mt=0;mt<4;mt++){
        u32 aH[4],aL[4];
        ldsm4(aH,ba+swz(rA+(u32)mt*16u,cA));
        ldsm4(aL,ba+16384u+swz(rA+(u32)mt*16u,cA));
        #pragma unroll
        for(int nn=0;nn<4;nn++){
          mma16816(acc[mt][2*nn],aH,bh[nn][0],bh[nn][1]);
          mma16816(acc[mt][2*nn+1],aH,bh[nn][2],bh[nn][3]);
        }
        if(THREE){
          #pragma unroll
          for(int nn=0;nn<4;nn++){
            mma16816(acc[mt][2*nn],aH,bl[nn][0],bl[nn][1]);
            mma16816(acc[mt][2*nn+1],aH,bl[nn][2],bl[nn][3]);
          }
        }
        #pragma unroll
        for(int nn=0;nn<4;nn++){
          mma16816(acc[mt][2*nn],aL,bh[nn][0],bh[nn][1]);
          mma16816(acc[mt][2*nn+1],aL,bh[nn][2],bh[nn][3]);
        }
      }
    }
  }
  #pragma unroll
  for(int mt=0;mt<4;mt++){
    int R0=bm+wm+mt*16+(t>>2);
    #pragma unroll
    for(int j=0;j<8;j++){
      int col=bn+wn+j*8+(t&3)*2;
      float c0=acc[mt][j][0],c1=acc[mt][j][1],c2=acc[mt][j][2],c3=acc[mt][j][3];
      if(Cf){
        float b0=bias[col],b1=bias[col+1];
        float2 v0; v0.x=c0+b0; v0.y=c1+b1;
        float2 v1; v1.x=c2+b0; v1.y=c3+b1;
        *(float2*)(Cf+(size_t)R0*D_+col)=v0;
        *(float2*)(Cf+(size_t)(R0+8)*D_+col)=v1;
      }else{
        __half h0,l0,h1,l1;
        spl(c0,h0,l0);spl(c1,h1,l1);
        *(u32*)(Ch+(size_t)R0*D_+col)=pkh(h0,h1);
        *(u32*)(Cl+(size_t)R0*D_+col)=pkh(l0,l1);
        spl(c2,h0,l0);spl(c3,h1,l1);
        *(u32*)(Ch+(size_t)(R0+8)*D_+col)=pkh(h0,h1);
        *(u32*)(Cl+(size_t)(R0+8)*D_+col)=pkh(l0,l1);
      }
    }
  }
}

// ---------------- HMMA attention (q=k=v), fixed-shift softmax, exact diag ----
// CTA: 64 q-rows, 128 thr. QK = Qh*Kh (1 term) + exact fp32 diagonal patch;
// PV = P*Vh. Diagonal s_ii = QS2*|q_i|^2 computed exactly per row. (R10 exact)
__global__ __launch_bounds__(128,2)
void attn_mma(const __half* __restrict__ qh,const __half* __restrict__ ql,
              __half* __restrict__ oh,__half* __restrict__ ol){
  extern __shared__ char smraw[];
  u32 sb=(s2u(smraw)+1023)&~1023u;
  const int tid=threadIdx.x,t=tid&31,w=tid>>5;
  const int mi=w>>1,ni=w&1;
  const int qt=blockIdx.x,hb=blockIdx.y,b=hb>>4,h=hb&15;
  const size_t base=(size_t)b*S_*D_+(size_t)h*64;
  const int q0=qt*64;
  const int dkt=qt>>1;                 // kt tile containing the diagonal
  const int off=(qt&1)*64;             // q-row offset within that tile
  const u32 LD=sb+8192;                // exact diag values [64] f32
  const u32 KB=sb+9216;                // K tiles (2 x 16KB double buffer)
  float* Ldp=(float*)(smraw+(LD-s2u(smraw)));
  // Q: combine h+l in fp32, scale by QS2, store HI half only (K-major SW)
  {
    const __half* gqh=qh+base+(size_t)q0*D_;
    const __half* gql=ql+base+(size_t)q0*D_;
    #pragma unroll
    for(int j=0;j<4;j++){int it=tid+128*j;u32 r=(u32)(it>>3),c=(u32)(it&7);
      uint4 vh4=*(const uint4*)(gqh+(size_t)r*D_+c*8);
      uint4 vl4=*(const uint4*)(gql+(size_t)r*D_+c*8);
      const __half* hv=(const __half*)&vh4; const __half* lv=(const __half*)&vl4;
      u32 wh[4];
      #pragma unroll
      for(int e=0;e<4;e++){
        float a0=(__half2float(hv[2*e])+__half2float(lv[2*e]))*QS2;
        float a1=(__half2float(hv[2*e+1])+__half2float(lv[2*e+1]))*QS2;
        wh[e]=pkf(a0,a1);
      }
      u32 d0=sb+swz(r,c);
      asm volatile("st.shared.v4.b32 [%0],{%1,%2,%3,%4};"::"r"(d0),"r"(wh[0]),"r"(wh[1]),"r"(wh[2]),"r"(wh[3]):"memory");
    }
  }
  // Exact diagonal: row=tid>>1, each half-thread sums 32 dims of (qh+ql)^2
  {
    int r=tid>>1, hf=tid&1;
    const __half* ph=qh+base+(size_t)(q0+r)*D_+hf*32;
    const __half* pl2=ql+base+(size_t)(q0+r)*D_+hf*32;
    float acc2=0.f;
    #pragma unroll
    for(int c=0;c<4;c++){
      uint4 vh4=*(const uint4*)(ph+c*8);
      uint4 vl4=*(const uint4*)(pl2+c*8);
      const __half* hv=(const __half*)&vh4; const __half* lv=(const __half*)&vl4;
      #pragma unroll
      for(int e=0;e<8;e++){
        float v=__half2float(hv[e])+__half2float(lv[e]);
        acc2+=v*v;
      }
    }
    acc2+=__shfl_xor_sync(0xffffffffu,acc2,1);
    if(hf==0) Ldp[r]=acc2*QS2;
  }
  // prefetch K tile 0 (hi half only)
  {
    const __half* gpk=qh+base;
    #pragma unroll
    for(int j=0;j<8;j++){int it=tid+128*j;u32 r=(u32)(it>>3),c=(u32)(it&7);
      cpa(KB+swz(r,c),gpk+(size_t)r*D_+c*8);}
  }
  CPC();
  float o[2][8][4]; float ls[4]={0.f,0.f,0.f,0.f};
  #pragma unroll
  for(int a=0;a<2;a++)for(int j=0;j<8;j++)for(int e=0;e<4;e++)o[a][j][e]=0.f;
  #pragma unroll 1
  for(int kt=0;kt<16;kt++){
    __syncthreads();
    if(kt<15){
      u32 st=(u32)((kt+1)&1);
      const __half* gpk=qh+base+(size_t)((kt+1)*128)*D_;
      #pragma unroll
      for(int j=0;j<8;j++){int it=tid+128*j;u32 r=(u32)(it>>3),c=(u32)(it&7);
        cpa(KB+st*16384+swz(r,c),gpk+(size_t)r*D_+c*8);}
      CPC(); CPW1();
    } else CPW0();
    __syncthreads();
    u32 kb=KB+(u32)(kt&1)*16384;
    float s[2][8][4];
    #pragma unroll
    for(int a=0;a<2;a++)for(int j=0;j<8;j++)for(int e=0;e<4;e++)s[a][j][e]=0.f;
    u32 rA=(u32)(mi*32+(t&7)+((t>>3)&1)*8);
    u32 rBb=(u32)(ni*64+(t&7)+((t>>4)<<3));
    #pragma unroll
    for(int k16=0;k16<4;k16++){
      u32 qf[2][4];
      u32 cA=(u32)(k16*2+(t>>4));
      ldsm4(qf[0],sb+swz(rA,cA));
      ldsm4(qf[1],sb+swz(rA+16,cA));
      u32 cB=(u32)(k16*2+((t>>3)&1));
      u32 bh[4][4];
      #pragma unroll
      for(int jj=0;jj<4;jj++) ldsm4(bh[jj],kb+swz(rBb+jj*16,cB));
      #pragma unroll
      for(int jj=0;jj<4;jj++)
        #pragma unroll
        for(int mt=0;mt<2;mt++){
          mma16816(s[mt][2*jj],qf[mt],bh[jj][0],bh[jj][1]);
          mma16816(s[mt][2*jj+1],qf[mt],bh[jj][2],bh[jj][3]);
        }
    }
    // exact diagonal patch (one kt per CTA)
    if(kt==dkt){
      #pragma unroll
      for(int mt=0;mt<2;mt++)
        #pragma unroll
        for(int j=0;j<8;j++)
          #pragma unroll
          for(int e=0;e<4;e++){
            int rl=mi*32+mt*16+(t>>2)+((e>>1)<<3);
            int cl=ni*64+j*8+(t&3)*2+(e&1);
            if(rl+off==cl) s[mt][j][e]=Ldp[rl];
          }
    }
    u32 pl[2][8][2];
    #pragma unroll
    for(int mt=0;mt<2;mt++)
      #pragma unroll
      for(int j=0;j<8;j++){
        float p0=ex2(s[mt][j][0]-SHIFT2),p1=ex2(s[mt][j][1]-SHIFT2);
        float p2=ex2(s[mt][j][2]-SHIFT2),p3=ex2(s[mt][j][3]-SHIFT2);
        ls[mt*2]+=p0+p1; ls[mt*2+1]+=p2+p3;
        pl[mt][j][0]=pkf(p0,p1); pl[mt][j][1]=pkf(p2,p3);
      }
    u32 rV0=(u32)(ni*64+(t&7)+((t>>3)&1)*8);
    #pragma unroll
    for(int kc=0;kc<4;kc++){
      u32 rV=rV0+kc*16;
      u32 af[2][4];
      #pragma unroll
      for(int mt=0;mt<2;mt++){
        af[mt][0]=pl[mt][2*kc][0]; af[mt][1]=pl[mt][2*kc][1];
        af[mt][2]=pl[mt][2*kc+1][0]; af[mt][3]=pl[mt][2*kc+1][1];
      }
      #pragma unroll
      for(int nn=0;nn<4;nn++){
        u32 cV=(u32)(nn*2+(t>>4));
        u32 vh[4];
        ldsm4t(vh,kb+swz(rV,cV));
        #pragma unroll
        for(int mt=0;mt<2;mt++){
          mma16816(o[mt][2*nn],af[mt],vh[0],vh[1]);
          mma16816(o[mt][2*nn+1],af[mt],vh[2],vh[3]);
        }
      }
    }
  }
  __syncthreads();
  #pragma unroll
  for(int e=0;e<4;e++){
    ls[e]+=__shfl_xor_sync(0xffffffffu,ls[e],1);
    ls[e]+=__shfl_xor_sync(0xffffffffu,ls[e],2);
  }
  u32 Osm=KB, Lsm=sb;
  if(ni==1){
    #pragma unroll
    for(int mt=0;mt<2;mt++){
      int r0=mi*32+mt*16+(t>>2);
      #pragma unroll
      for(int j=0;j<8;j++){
        int c=j*8+(t&3)*2;
        asm volatile("st.shared.v2.f32 [%0],{%1,%2};"::"r"(Osm+(u32)((r0*64+c)*4)),"f"(o[mt][j][0]),"f"(o[mt][j][1]):"memory");
        asm volatile("st.shared.v2.f32 [%0],{%1,%2};"::"r"(Osm+(u32)(((r0+8)*64+c)*4)),"f"(o[mt][j][2]),"f"(o[mt][j][3]):"memory");
      }
      if((t&3)==0){
        asm volatile("st.shared.f32 [%0],%1;"::"r"(Lsm+(u32)(r0*4)),"f"(ls[mt*2]):"memory");
        asm volatile("st.shared.f32 [%0],%1;"::"r"(Lsm+(u32)((r0+8)*4)),"f"(ls[mt*2+1]):"memory");
      }
    }
  }
  __syncthreads();
  if(ni==0){
    #pragma unroll
    for(int mt=0;mt<2;mt++){
      int rloc=mi*32+mt*16+(t>>2);
      float lA,lB;
      asm volatile("ld.shared.f32 %0,[%1];":"=f"(lA):"r"(Lsm+(u32)(rloc*4)));
      asm volatile("ld.shared.f32 %0,[%1];":"=f"(lB):"r"(Lsm+(u32)((rloc+8)*4)));
      float iA=1.f/(ls[mt*2]+lA), iB=1.f/(ls[mt*2+1]+lB);
      size_t R0=base+(size_t)(q0+rloc)*D_;
      size_t R1=base+(size_t)(q0+rloc+8)*D_;
      #pragma unroll
      for(int j=0;j<8;j++){
        int c=j*8+(t&3)*2;
        float a0,a1,b0f,b1f;
        asm volatile("ld.shared.v2.f32 {%0,%1},[%2];":"=f"(a0),"=f"(a1):"r"(Osm+(u32)((rloc*64+c)*4)));
        asm volatile("ld.shared.v2.f32 {%0,%1},[%2];":"=f"(b0f),"=f"(b1f):"r"(Osm+(u32)(((rloc+8)*64+c)*4)));
        float v0=(o[mt][j][0]+a0)*iA, v1=(o[mt][j][1]+a1)*iA;
        float v2=(o[mt][j][2]+b0f)*iB, v3=(o[mt][j][3]+b1f)*iB;
        __half h0,l0,h1,l1;
        spl(v0,h0,l0);spl(v1,h1,l1);
        *(u32*)(oh+R0+c)=pkh(h0,h1); *(u32*)(ol+R0+c)=pkh(l0,l1);
        spl(v2,h0,l0);spl(v3,h1,l1);
        *(u32*)(oh+R1+c)=pkh(h0,h1); *(u32*)(ol+R1+c)=pkh(l0,l1);
      }
    }
  }
}

// ---------------------------------------------------------------------------
extern "C" void kernel_launch(void* const* d_in, const int* in_sizes, int n_in,
                              void* d_out, int out_size) {
    const float* x=(const float*)d_in[0];
    const float* w_qkv=(const float*)d_in[1];
    const float* w_out=(const float*)d_in[2];
    const float* b_out=(const float*)d_in[3];
    float* out=(float*)d_out;

    __half *xh,*xl,*qh,*ql,*ah,*al,*wqh,*wql,*woh,*wol;
    cudaGetSymbolAddress((void**)&xh,g_xh);   cudaGetSymbolAddress((void**)&xl,g_xl);
    cudaGetSymbolAddress((void**)&qh,g_qh);   cudaGetSymbolAddress((void**)&ql,g_ql);
    cudaGetSymbolAddress((void**)&ah,g_ah);   cudaGetSymbolAddress((void**)&al,g_al);
    cudaGetSymbolAddress((void**)&wqh,g_wqh); cudaGetSymbolAddress((void**)&wql,g_wql);
    cudaGetSymbolAddress((void**)&woh,g_woh); cudaGetSymbolAddress((void**)&wol,g_wol);

    const int SMG3=196608+1024, SMG2=131072+1024, SMA=9216+32768+1024;
    cudaFuncSetAttribute(gemm_mma<true>,  cudaFuncAttributeMaxDynamicSharedMemorySize, SMG3);
    cudaFuncSetAttribute(gemm_mma<false>, cudaFuncAttributeMaxDynamicSharedMemorySize, SMG2);
    cudaFuncSetAttribute(attn_mma, cudaFuncAttributeMaxDynamicSharedMemorySize, SMA);

    split_k<<<(NT*D_)/1024,256>>>(x,xh,xl,NT*D_);
    split_k<<<(D_*D_)/1024,256>>>(w_qkv,wqh,wql,D_*D_);
    split_k<<<(D_*D_)/1024,256>>>(w_out,woh,wol,D_*D_);

    dim3 g1(D_/256, NT/128);             // (4, 64) = 256 CTAs
    gemm_mma<true><<<g1,256,SMG3>>>(xh,xl,wqh,wql,nullptr,qh,ql,nullptr);

    dim3 g2(S_/64, 64);                  // (32, 64)
    attn_mma<<<g2,128,SMA>>>(qh,ql,ah,al);

    gemm_mma<false><<<g1,256,SMG2>>>(ah,al,woh,nullptr,b_out,nullptr,nullptr,out);
}

// round 14
// speedup vs baseline: 1.1115x; 1.1054x over previous
#include <cuda_runtime.h>
#include <cuda_fp16.h>
#include <cstdint>

#define B_ 4
#define S_ 2048
#define D_ 1024
#define NT (B_*S_)
#define QS2    0.18033688011112042f   // 0.125 * log2(e)
#define SHIFT2 14.426950408889634f    // 10 * log2(e)
typedef uint32_t u32;

__device__ __half g_xh[(size_t)NT*D_], g_xl[(size_t)NT*D_];
__device__ __half g_qh[(size_t)NT*D_], g_ql[(size_t)NT*D_];
__device__ __half g_ah[(size_t)NT*D_];
__device__ __half g_wqh[D_*D_], g_wql[D_*D_], g_woh[D_*D_], g_wol[D_*D_];

__device__ __forceinline__ u32 s2u(const void* p){u32 a;asm("{.reg .u64 t;cvta.to.shared.u64 t,%1;cvt.u32.u64 %0,t;}":"=r"(a):"l"(p));return a;}
__device__ __forceinline__ u32 swz(u32 r,u32 c16){return r*128u+((c16^(r&7u))<<4);}
__device__ __forceinline__ void spl(float v,__half&h,__half&l){h=__float2half_rn(v);l=__float2half_rn(v-__half2float(h));}
__device__ __forceinline__ u32 pkh(__half a,__half b){__half2 t=__halves2half2(a,b);return *(u32*)&t;}
__device__ __forceinline__ u32 pkf(float a,float b){__half2 t=__floats2half2_rn(a,b);return *(u32*)&t;}
__device__ __forceinline__ float ex2(float x){float r;asm("ex2.approx.f32 %0,%1;":"=f"(r):"f"(x));return r;}
__device__ __forceinline__ void ldsm4(u32* r,u32 a){asm volatile("ldmatrix.sync.aligned.m8n8.x4.shared.b16 {%0,%1,%2,%3},[%4];":"=r"(r[0]),"=r"(r[1]),"=r"(r[2]),"=r"(r[3]):"r"(a));}
__device__ __forceinline__ void ldsm4t(u32* r,u32 a){asm volatile("ldmatrix.sync.aligned.m8n8.x4.trans.shared.b16 {%0,%1,%2,%3},[%4];":"=r"(r[0]),"=r"(r[1]),"=r"(r[2]),"=r"(r[3]):"r"(a));}
__device__ __forceinline__ void mma16816(float* c,const u32* a,u32 b0,u32 b1){
  asm volatile("mma.sync.aligned.m16n8k16.row.col.f32.f16.f16.f32 {%0,%1,%2,%3},{%4,%5,%6,%7},{%8,%9},{%0,%1,%2,%3};"
    :"+f"(c[0]),"+f"(c[1]),"+f"(c[2]),"+f"(c[3])
    :"r"(a[0]),"r"(a[1]),"r"(a[2]),"r"(a[3]),"r"(b0),"r"(b1));}
__device__ __forceinline__ void cpa(u32 d,const void* s){asm volatile("cp.async.cg.shared.global [%0],[%1],16;"::"r"(d),"l"(s):"memory");}
#define CPC()  asm volatile("cp.async.commit_group;":::"memory")
#define CPW0() asm volatile("cp.async.wait_group 0;":::"memory")
#define CPW1() asm volatile("cp.async.wait_group 1;":::"memory")

// ---------------- fp32 -> fp16 hi/lo split ----------------
__global__ void split_k(const float* __restrict__ s,__half* __restrict__ dh,__half* __restrict__ dl,int n){
    int i=(blockIdx.x*blockDim.x+threadIdx.x)*4; if(i>=n) return;
    float4 v=*(const float4*)(s+i);
    __half h0,h1,h2,h3,l0,l1,l2,l3;
    spl(v.x,h0,l0);spl(v.y,h1,l1);spl(v.z,h2,l2);spl(v.w,h3,l3);
    *(uint2*)(dh+i)=make_uint2(pkh(h0,h1),pkh(h2,h3));
    *(uint2*)(dl+i)=make_uint2(pkh(l0,l1),pkh(l2,l3));
}

// ---------------- HMMA GEMM: C = A*W^T (+bias) ----------------
// CTA 128(M)x256(N), K-chunk 64, 256 thr = 8 warps (2x4), warp tile 64x64.
// cp.async double buffer, warp-staggered k16, B frags preloaded per k16.
// TERMS=3: AhWh+AhWl+AlWh (fp16-split). TERMS=1: Ah*Wh.
template<int TERMS>
__global__ __launch_bounds__(256,1)
void gemm_mma(const __half* __restrict__ Ah,const __half* __restrict__ Al,
              const __half* __restrict__ Wh,const __half* __restrict__ Wl,
              const float* __restrict__ bias,
              __half* __restrict__ Ch,__half* __restrict__ Cl,float* __restrict__ Cf){
  extern __shared__ char smraw[];
  u32 sb=(s2u(smraw)+1023)&~1023u;
  const int tid=threadIdx.x,t=tid&31,w=tid>>5;
  const int bm=blockIdx.y*128,bn=blockIdx.x*256;
  const int wm=(w>>2)*64,wn=(w&3)*64;
  const bool THREE=(TERMS==3);
  // layout: Ah 16K, [Al 16K], Wh 32K, [Wl 32K]
  const u32 OFF_W = THREE?32768u:16384u;
  const u32 BUFSZ = THREE?98304u:49152u;
  float acc[4][8][4];
  #pragma unroll
  for(int a=0;a<4;a++)for(int j=0;j<8;j++)for(int e=0;e<4;e++)acc[a][j][e]=0.f;
  const __half* gA0=Ah+(size_t)bm*D_;
  const __half* gA1=THREE?(Al+(size_t)bm*D_):gA0;
  const __half* gW0=Wh+(size_t)bn*D_;
  const __half* gW1=THREE?(Wl+(size_t)bn*D_):gW0;

  #pragma unroll
  for(int j=0;j<4;j++){int it=tid+256*j;u32 r=(u32)(it>>3),c=(u32)(it&7);
    cpa(sb+swz(r,c),gA0+(size_t)r*D_+c*8);
    if(THREE) cpa(sb+16384u+swz(r,c),gA1+(size_t)r*D_+c*8);}
  #pragma unroll
  for(int j=0;j<8;j++){int it=tid+256*j;u32 r=(u32)(it>>3),c=(u32)(it&7);
    cpa(sb+OFF_W+swz(r,c),gW0+(size_t)r*D_+c*8);
    if(THREE) cpa(sb+65536u+swz(r,c),gW1+(size_t)r*D_+c*8);}
  CPC();

  #pragma unroll 1
  for(int kc=0;kc<16;kc++){
    __syncthreads();
    if(kc<15){
      u32 bufb=sb+(u32)((kc+1)&1)*BUFSZ; int k0=(kc+1)*64;
      #pragma unroll
      for(int j=0;j<4;j++){int it=tid+256*j;u32 r=(u32)(it>>3),c=(u32)(it&7);
        cpa(bufb+swz(r,c),gA0+(size_t)r*D_+k0+c*8);
        if(THREE) cpa(bufb+16384u+swz(r,c),gA1+(size_t)r*D_+k0+c*8);}
      #pragma unroll
      for(int j=0;j<8;j++){int it=tid+256*j;u32 r=(u32)(it>>3),c=(u32)(it&7);
        cpa(bufb+OFF_W+swz(r,c),gW0+(size_t)r*D_+k0+c*8);
        if(THREE) cpa(bufb+65536u+swz(r,c),gW1+(size_t)r*D_+k0+c*8);}
      CPC(); CPW1();
    } else CPW0();
    __syncthreads();
    u32 ba=sb+(u32)(kc&1)*BUFSZ;
    #pragma unroll
    for(int kx=0;kx<4;kx++){
      int k16=(kx+(w&3))&3;               // warp-staggered K order
      u32 rA=(u32)(wm+(t&7)+((t>>3)&1)*8);
      u32 cA=(u32)(k16*2+(t>>4));
      u32 rB=(u32)(wn+(t&7)+((t>>4)<<3));
      u32 cB=(u32)(k16*2+((t>>3)&1));
      u32 bh[4][4],bl[4][4];
      #pragma unroll
      for(int nn=0;nn<4;nn++){
        ldsm4(bh[nn],ba+OFF_W+swz(rB+(u32)nn*16u,cB));
        if(THREE) ldsm4(bl[nn],ba+65536u+swz(rB+(u32)nn*16u,cB));
      }
      #pragma unroll
      for(int mt=0;mt<4;mt++){
        u32 aH[4],aL[4];
        ldsm4(aH,ba+swz(rA+(u32)mt*16u,cA));
        if(THREE) ldsm4(aL,ba+16384u+swz(rA+(u32)mt*16u,cA));
        #pragma unroll
        for(int nn=0;nn<4;nn++){
          mma16816(acc[mt][2*nn],aH,bh[nn][0],bh[nn][1]);
          mma16816(acc[mt][2*nn+1],aH,bh[nn][2],bh[nn][3]);
        }
        if(THREE){
          #pragma unroll
          for(int nn=0;nn<4;nn++){
            mma16816(acc[mt][2*nn],aH,bl[nn][0],bl[nn][1]);
            mma16816(acc[mt][2*nn+1],aH,bl[nn][2],bl[nn][3]);
          }
          #pragma unroll
          for(int nn=0;nn<4;nn++){
            mma16816(acc[mt][2*nn],aL,bh[nn][0],bh[nn][1]);
            mma16816(acc[mt][2*nn+1],aL,bh[nn][2],bh[nn][3]);
          }
        }
      }
    }
  }
  #pragma unroll
  for(int mt=0;mt<4;mt++){
    int R0=bm+wm+mt*16+(t>>2);
    #pragma unroll
    for(int j=0;j<8;j++){
      int col=bn+wn+j*8+(t&3)*2;
      float c0=acc[mt][j][0],c1=acc[mt][j][1],c2=acc[mt][j][2],c3=acc[mt][j][3];
      if(Cf){
        float b0=bias[col],b1=bias[col+1];
        float2 v0; v0.x=c0+b0; v0.y=c1+b1;
        float2 v1; v1.x=c2+b0; v1.y=c3+b1;
        *(float2*)(Cf+(size_t)R0*D_+col)=v0;
        *(float2*)(Cf+(size_t)(R0+8)*D_+col)=v1;
      }else{
        __half h0,l0,h1,l1;
        spl(c0,h0,l0);spl(c1,h1,l1);
        *(u32*)(Ch+(size_t)R0*D_+col)=pkh(h0,h1);
        *(u32*)(Cl+(size_t)R0*D_+col)=pkh(l0,l1);
        spl(c2,h0,l0);spl(c3,h1,l1);
        *(u32*)(Ch+(size_t)(R0+8)*D_+col)=pkh(h0,h1);
        *(u32*)(Cl+(size_t)(R0+8)*D_+col)=pkh(l0,l1);
      }
    }
  }
}

// ---------------- HMMA attention (q=k=v), fixed-shift softmax, exact diag ----
// CTA: 64 q-rows, 128 thr. QK = Qh*Kh + exact fp32 diagonal; PV = P*Vh.
// Q fragments hoisted to registers (kt-invariant). O written as single fp16.
__global__ __launch_bounds__(128,2)
void attn_mma(const __half* __restrict__ qh,const __half* __restrict__ ql,
              __half* __restrict__ oh){
  extern __shared__ char smraw[];
  u32 sb=(s2u(smraw)+1023)&~1023u;
  const int tid=threadIdx.x,t=tid&31,w=tid>>5;
  const int mi=w>>1,ni=w&1;
  const int qt=blockIdx.x,hb=blockIdx.y,b=hb>>4,h=hb&15;
  const size_t base=(size_t)b*S_*D_+(size_t)h*64;
  const int q0=qt*64;
  const int dkt=qt>>1;                 // kt tile containing the diagonal
  const int off=(qt&1)*64;             // q-row offset within that tile
  const u32 LD=sb+8192;                // exact diag values [64] f32
  const u32 KB=sb+9216;                // K tiles (2 x 16KB double buffer)
  float* Ldp=(float*)(smraw+(LD-s2u(smraw)));
  // Q: combine h+l in fp32, scale by QS2, store fp16 to smem (K-major SW)
  {
    const __half* gqh=qh+base+(size_t)q0*D_;
    const __half* gql=ql+base+(size_t)q0*D_;
    #pragma unroll
    for(int j=0;j<4;j++){int it=tid+128*j;u32 r=(u32)(it>>3),c=(u32)(it&7);
      uint4 vh4=*(const uint4*)(gqh+(size_t)r*D_+c*8);
      uint4 vl4=*(const uint4*)(gql+(size_t)r*D_+c*8);
      const __half* hv=(const __half*)&vh4; const __half* lv=(const __half*)&vl4;
      u32 wh[4];
      #pragma unroll
      for(int e=0;e<4;e++){
        float a0=(__half2float(hv[2*e])+__half2float(lv[2*e]))*QS2;
        float a1=(__half2float(hv[2*e+1])+__half2float(lv[2*e+1]))*QS2;
        wh[e]=pkf(a0,a1);
      }
      u32 d0=sb+swz(r,c);
      asm volatile("st.shared.v4.b32 [%0],{%1,%2,%3,%4};"::"r"(d0),"r"(wh[0]),"r"(wh[1]),"r"(wh[2]),"r"(wh[3]):"memory");
    }
  }
  // Exact diagonal: row=tid>>1, each half-thread sums 32 dims of (qh+ql)^2
  {
    int r=tid>>1, hf=tid&1;
    const __half* ph=qh+base+(size_t)(q0+r)*D_+hf*32;
    const __half* pl2=ql+base+(size_t)(q0+r)*D_+hf*32;
    float acc2=0.f;
    #pragma unroll
    for(int c=0;c<4;c++){
      uint4 vh4=*(const uint4*)(ph+c*8);
      uint4 vl4=*(const uint4*)(pl2+c*8);
      const __half* hv=(const __half*)&vh4; const __half* lv=(const __half*)&vl4;
      #pragma unroll
      for(int e=0;e<8;e++){
        float v=__half2float(hv[e])+__half2float(lv[e]);
        acc2+=v*v;
      }
    }
    acc2+=__shfl_xor_sync(0xffffffffu,acc2,1);
    if(hf==0) Ldp[r]=acc2*QS2;
  }
  // prefetch K tile 0 (hi half only)
  {
    const __half* gpk=qh+base;
    #pragma unroll
    for(int j=0;j<8;j++){int it=tid+128*j;u32 r=(u32)(it>>3),c=(u32)(it&7);
      cpa(KB+swz(r,c),gpk+(size_t)r*D_+c*8);}
  }
  CPC();
  // hoist Q fragments (kt-invariant) into registers
  __syncthreads();
  u32 qf[4][2][4];
  {
    u32 rA=(u32)(mi*32+(t&7)+((t>>3)&1)*8);
    #pragma unroll
    for(int k16=0;k16<4;k16++){
      u32 cA=(u32)(k16*2+(t>>4));
      ldsm4(qf[k16][0],sb+swz(rA,cA));
      ldsm4(qf[k16][1],sb+swz(rA+16,cA));
    }
  }
  float o[2][8][4]; float ls[4]={0.f,0.f,0.f,0.f};
  #pragma unroll
  for(int a=0;a<2;a++)for(int j=0;j<8;j++)for(int e=0;e<4;e++)o[a][j][e]=0.f;
  #pragma unroll 1
  for(int kt=0;kt<16;kt++){
    __syncthreads();
    if(kt<15){
      u32 st=(u32)((kt+1)&1);
      const __half* gpk=qh+base+(size_t)((kt+1)*128)*D_;
      #pragma unroll
      for(int j=0;j<8;j++){int it=tid+128*j;u32 r=(u32)(it>>3),c=(u32)(it&7);
        cpa(KB+st*16384+swz(r,c),gpk+(size_t)r*D_+c*8);}
      CPC(); CPW1();
    } else CPW0();
    __syncthreads();
    u32 kb=KB+(u32)(kt&1)*16384;
    float s[2][8][4];
    #pragma unroll
    for(int a=0;a<2;a++)for(int j=0;j<8;j++)for(int e=0;e<4;e++)s[a][j][e]=0.f;
    u32 rBb=(u32)(ni*64+(t&7)+((t>>4)<<3));
    #pragma unroll
    for(int k16=0;k16<4;k16++){
      u32 cB=(u32)(k16*2+((t>>3)&1));
      u32 bh[4][4];
      #pragma unroll
      for(int jj=0;jj<4;jj++) ldsm4(bh[jj],kb+swz(rBb+jj*16,cB));
      #pragma unroll
      for(int jj=0;jj<4;jj++)
        #pragma unroll
        for(int mt=0;mt<2;mt++){
          mma16816(s[mt][2*jj],qf[k16][mt],bh[jj][0],bh[jj][1]);
          mma16816(s[mt][2*jj+1],qf[k16][mt],bh[jj][2],bh[jj][3]);
        }
    }
    // exact diagonal patch (one kt per CTA)
    if(kt==dkt){
      #pragma unroll
      for(int mt=0;mt<2;mt++)
        #pragma unroll
        for(int j=0;j<8;j++)
          #pragma unroll
          for(int e=0;e<4;e++){
            int rl=mi*32+mt*16+(t>>2)+((e>>1)<<3);
            int cl=ni*64+j*8+(t&3)*2+(e&1);
            if(rl+off==cl) s[mt][j][e]=Ldp[rl];
          }
    }
    u32 pl[2][8][2];
    #pragma unroll
    for(int mt=0;mt<2;mt++)
      #pragma unroll
      for(int j=0;j<8;j++){
        float p0=ex2(s[mt][j][0]-SHIFT2),p1=ex2(s[mt][j][1]-SHIFT2);
        float p2=ex2(s[mt][j][2]-SHIFT2),p3=ex2(s[mt][j][3]-SHIFT2);
        ls[mt*2]+=p0+p1; ls[mt*2+1]+=p2+p3;
        pl[mt][j][0]=pkf(p0,p1); pl[mt][j][1]=pkf(p2,p3);
      }
    u32 rV0=(u32)(ni*64+(t&7)+((t>>3)&1)*8);
    #pragma unroll
    for(int kc=0;kc<4;kc++){
      u32 rV=rV0+kc*16;
      u32 af[2][4];
      #pragma unroll
      for(int mt=0;mt<2;mt++){
        af[mt][0]=pl[mt][2*kc][0]; af[mt][1]=pl[mt][2*kc][1];
        af[mt][2]=pl[mt][2*kc+1][0]; af[mt][3]=pl[mt][2*kc+1][1];
      }
      #pragma unroll
      for(int nn=0;nn<4;nn++){
        u32 cV=(u32)(nn*2+(t>>4));
        u32 vh[4];
        ldsm4t(vh,kb+swz(rV,cV));
        #pragma unroll
        for(int mt=0;mt<2;mt++){
          mma16816(o[mt][2*nn],af[mt],vh[0],vh[1]);
          mma16816(o[mt][2*nn+1],af[mt],vh[2],vh[3]);
        }
      }
    }
  }
  __syncthreads();
  #pragma unroll
  for(int e=0;e<4;e++){
    ls[e]+=__shfl_xor_sync(0xffffffffu,ls[e],1);
    ls[e]+=__shfl_xor_sync(0xffffffffu,ls[e],2);
  }
  u32 Osm=KB, Lsm=sb;
  if(ni==1){
    #pragma unroll
    for(int mt=0;mt<2;mt++){
      int r0=mi*32+mt*16+(t>>2);
      #pragma unroll
      for(int j=0;j<8;j++){
        int c=j*8+(t&3)*2;
        asm volatile("st.shared.v2.f32 [%0],{%1,%2};"::"r"(Osm+(u32)((r0*64+c)*4)),"f"(o[mt][j][0]),"f"(o[mt][j][1]):"memory");
        asm volatile("st.shared.v2.f32 [%0],{%1,%2};"::"r"(Osm+(u32)(((r0+8)*64+c)*4)),"f"(o[mt][j][2]),"f"(o[mt][j][3]):"memory");
      }
      if((t&3)==0){
        asm volatile("st.shared.f32 [%0],%1;"::"r"(Lsm+(u32)(r0*4)),"f"(ls[mt*2]):"memory");
        asm volatile("st.shared.f32 [%0],%1;"::"r"(Lsm+(u32)((r0+8)*4)),"f"(ls[mt*2+1]):"memory");
      }
    }
  }
  __syncthreads();
  if(ni==0){
    #pragma unroll
    for(int mt=0;mt<2;mt++){
      int rloc=mi*32+mt*16+(t>>2);
      float lA,lB;
      asm volatile("ld.shared.f32 %0,[%1];":"=f"(lA):"r"(Lsm+(u32)(rloc*4)));
      asm volatile("ld.shared.f32 %0,[%1];":"=f"(lB):"r"(Lsm+(u32)((rloc+8)*4)));
      float iA=1.f/(ls[mt*2]+lA), iB=1.f/(ls[mt*2+1]+lB);
      size_t R0=base+(size_t)(q0+rloc)*D_;
      size_t R1=base+(size_t)(q0+rloc+8)*D_;
      #pragma unroll
      for(int j=0;j<8;j++){
        int c=j*8+(t&3)*2;
        float a0,a1,b0f,b1f;
        asm volatile("ld.shared.v2.f32 {%0,%1},[%2];":"=f"(a0),"=f"(a1):"r"(Osm+(u32)((rloc*64+c)*4)));
        asm volatile("ld.shared.v2.f32 {%0,%1},[%2];":"=f"(b0f),"=f"(b1f):"r"(Osm+(u32)(((rloc+8)*64+c)*4)));
        float v0=(o[mt][j][0]+a0)*iA, v1=(o[mt][j][1]+a1)*iA;
        float v2=(o[mt][j][2]+b0f)*iB, v3=(o[mt][j][3]+b1f)*iB;
        *(u32*)(oh+R0+c)=pkf(v0,v1);
        *(u32*)(oh+R1+c)=pkf(v2,v3);
      }
    }
  }
}

// ---------------------------------------------------------------------------
extern "C" void kernel_launch(void* const* d_in, const int* in_sizes, int n_in,
                              void* d_out, int out_size) {
    const float* x=(const float*)d_in[0];
    const float* w_qkv=(const float*)d_in[1];
    const float* w_out=(const float*)d_in[2];
    const float* b_out=(const float*)d_in[3];
    float* out=(float*)d_out;

    __half *xh,*xl,*qh,*ql,*ah,*wqh,*wql,*woh,*wol;
    cudaGetSymbolAddress((void**)&xh,g_xh);   cudaGetSymbolAddress((void**)&xl,g_xl);
    cudaGetSymbolAddress((void**)&qh,g_qh);   cudaGetSymbolAddress((void**)&ql,g_ql);
    cudaGetSymbolAddress((void**)&ah,g_ah);
    cudaGetSymbolAddress((void**)&wqh,g_wqh); cudaGetSymbolAddress((void**)&wql,g_wql);
    cudaGetSymbolAddress((void**)&woh,g_woh); cudaGetSymbolAddress((void**)&wol,g_wol);

    const int SMG3=196608+1024, SMG1=98304+1024, SMA=9216+32768+1024;
    cudaFuncSetAttribute(gemm_mma<3>, cudaFuncAttributeMaxDynamicSharedMemorySize, SMG3);
    cudaFuncSetAttribute(gemm_mma<1>, cudaFuncAttributeMaxDynamicSharedMemorySize, SMG1);
    cudaFuncSetAttribute(attn_mma, cudaFuncAttributeMaxDynamicSharedMemorySize, SMA);

    split_k<<<(NT*D_)/1024,256>>>(x,xh,xl,NT*D_);
    split_k<<<(D_*D_)/1024,256>>>(w_qkv,wqh,wql,D_*D_);
    split_k<<<(D_*D_)/1024,256>>>(w_out,woh,wol,D_*D_);

    dim3 g1(D_/256, NT/128);             // (4, 64) = 256 CTAs
    gemm_mma<3><<<g1,256,SMG3>>>(xh,xl,wqh,wql,nullptr,qh,ql,nullptr);

    dim3 g2(S_/64, 64);                  // (32, 64)
    attn_mma<<<g2,128,SMA>>>(qh,ql,ah);

    gemm_mma<1><<<g1,256,SMG1>>>(ah,nullptr,woh,nullptr,b_out,nullptr,nullptr,out);
}

// round 15
// speedup vs baseline: 1.2662x; 1.1392x over previous
#include <cuda_runtime.h>
#include <cuda_fp16.h>
#include <cstdint>

#define B_ 4
#define S_ 2048
#define D_ 1024
#define NT (B_*S_)
#define QS2    0.18033688011112042f   // 0.125 * log2(e)
#define SHIFT2 14.426950408889634f    // 10 * log2(e)
typedef uint32_t u32;

__device__ __half g_xh[(size_t)NT*D_];
__device__ __half g_qh[(size_t)NT*D_], g_ql[(size_t)NT*D_];
__device__ __half g_ah[(size_t)NT*D_];
__device__ __half g_wqh[D_*D_], g_wql[D_*D_], g_woh[D_*D_], g_wol[D_*D_];

__device__ __forceinline__ u32 s2u(const void* p){u32 a;asm("{.reg .u64 t;cvta.to.shared.u64 t,%1;cvt.u32.u64 %0,t;}":"=r"(a):"l"(p));return a;}
__device__ __forceinline__ u32 swz(u32 r,u32 c16){return r*128u+((c16^(r&7u))<<4);}
__device__ __forceinline__ void spl(float v,__half&h,__half&l){h=__float2half_rn(v);l=__float2half_rn(v-__half2float(h));}
__device__ __forceinline__ u32 pkh(__half a,__half b){__half2 t=__halves2half2(a,b);return *(u32*)&t;}
__device__ __forceinline__ u32 pkf(float a,float b){__half2 t=__floats2half2_rn(a,b);return *(u32*)&t;}
__device__ __forceinline__ float ex2(float x){float r;asm("ex2.approx.f32 %0,%1;":"=f"(r):"f"(x));return r;}
__device__ __forceinline__ void ldsm4(u32* r,u32 a){asm volatile("ldmatrix.sync.aligned.m8n8.x4.shared.b16 {%0,%1,%2,%3},[%4];":"=r"(r[0]),"=r"(r[1]),"=r"(r[2]),"=r"(r[3]):"r"(a));}
__device__ __forceinline__ void ldsm4t(u32* r,u32 a){asm volatile("ldmatrix.sync.aligned.m8n8.x4.trans.shared.b16 {%0,%1,%2,%3},[%4];":"=r"(r[0]),"=r"(r[1]),"=r"(r[2]),"=r"(r[3]):"r"(a));}
__device__ __forceinline__ void mma16816(float* c,const u32* a,u32 b0,u32 b1){
  asm volatile("mma.sync.aligned.m16n8k16.row.col.f32.f16.f16.f32 {%0,%1,%2,%3},{%4,%5,%6,%7},{%8,%9},{%0,%1,%2,%3};"
    :"+f"(c[0]),"+f"(c[1]),"+f"(c[2]),"+f"(c[3])
    :"r"(a[0]),"r"(a[1]),"r"(a[2]),"r"(a[3]),"r"(b0),"r"(b1));}
__device__ __forceinline__ void cpa(u32 d,const void* s){asm volatile("cp.async.cg.shared.global [%0],[%1],16;"::"r"(d),"l"(s):"memory");}
#define CPC()  asm volatile("cp.async.commit_group;":::"memory")
#define CPW0() asm volatile("cp.async.wait_group 0;":::"memory")
#define CPW1() asm volatile("cp.async.wait_group 1;":::"memory")

// ---------------- fp32 -> fp16 hi/lo split ----------------
__global__ void split_k(const float* __restrict__ s,__half* __restrict__ dh,__half* __restrict__ dl,int n){
    int i=(blockIdx.x*blockDim.x+threadIdx.x)*4; if(i>=n) return;
    float4 v=*(const float4*)(s+i);
    __half h0,h1,h2,h3,l0,l1,l2,l3;
    spl(v.x,h0,l0);spl(v.y,h1,l1);spl(v.z,h2,l2);spl(v.w,h3,l3);
    *(uint2*)(dh+i)=make_uint2(pkh(h0,h1),pkh(h2,h3));
    *(uint2*)(dl+i)=make_uint2(pkh(l0,l1),pkh(l2,l3));
}
// fp32 -> fp16 (hi only)
__global__ void split_h(const float* __restrict__ s,__half* __restrict__ dh,int n){
    int i=(blockIdx.x*blockDim.x+threadIdx.x)*4; if(i>=n) return;
    float4 v=*(const float4*)(s+i);
    *(uint2*)(dh+i)=make_uint2(pkf(v.x,v.y),pkf(v.z,v.w));
}

// ---------------- HMMA GEMM: C = A*W^T (+bias) ----------------
// CTA 128(M)x256(N), K-chunk 64, 256 thr = 8 warps (2x4), warp tile 64x64.
// cp.async double buffer, warp-staggered k16, B frags preloaded per k16.
// TERMS=3: AhWh+AhWl+AlWh.  TERMS=2: AhWh+AhWl.  TERMS=1: AhWh.
template<int TERMS>
__global__ __launch_bounds__(256,1)
void gemm_mma(const __half* __restrict__ Ah,const __half* __restrict__ Al,
              const __half* __restrict__ Wh,const __half* __restrict__ Wl,
              const float* __restrict__ bias,
              __half* __restrict__ Ch,__half* __restrict__ Cl,float* __restrict__ Cf){
  extern __shared__ char smraw[];
  u32 sb=(s2u(smraw)+1023)&~1023u;
  const int tid=threadIdx.x,t=tid&31,w=tid>>5;
  const int bm=blockIdx.y*128,bn=blockIdx.x*256;
  const int wm=(w>>2)*64,wn=(w&3)*64;
  const bool THREE=(TERMS==3), WLO=(TERMS>=2);
  // layout: Ah 16K, [Al 16K if THREE], Wh 32K, [Wl 32K if TERMS>=2]
  const u32 OFF_W0 = THREE?32768u:16384u;
  const u32 OFF_W1 = OFF_W0+32768u;
  const u32 BUFSZ  = THREE?98304u:(WLO?81920u:49152u);
  float acc[4][8][4];
  #pragma unroll
  for(int a=0;a<4;a++)for(int j=0;j<8;j++)for(int e=0;e<4;e++)acc[a][j][e]=0.f;
  const __half* gA0=Ah+(size_t)bm*D_;
  const __half* gA1=THREE?(Al+(size_t)bm*D_):gA0;
  const __half* gW0=Wh+(size_t)bn*D_;
  const __half* gW1=WLO?(Wl+(size_t)bn*D_):gW0;

  #pragma unroll
  for(int j=0;j<4;j++){int it=tid+256*j;u32 r=(u32)(it>>3),c=(u32)(it&7);
    cpa(sb+swz(r,c),gA0+(size_t)r*D_+c*8);
    if(THREE) cpa(sb+16384u+swz(r,c),gA1+(size_t)r*D_+c*8);}
  #pragma unroll
  for(int j=0;j<8;j++){int it=tid+256*j;u32 r=(u32)(it>>3),c=(u32)(it&7);
    cpa(sb+OFF_W0+swz(r,c),gW0+(size_t)r*D_+c*8);
    if(WLO) cpa(sb+OFF_W1+swz(r,c),gW1+(size_t)r*D_+c*8);}
  CPC();

  #pragma unroll 1
  for(int kc=0;kc<16;kc++){
    __syncthreads();
    if(kc<15){
      u32 bufb=sb+(u32)((kc+1)&1)*BUFSZ; int k0=(kc+1)*64;
      #pragma unroll
      for(int j=0;j<4;j++){int it=tid+256*j;u32 r=(u32)(it>>3),c=(u32)(it&7);
        cpa(bufb+swz(r,c),gA0+(size_t)r*D_+k0+c*8);
        if(THREE) cpa(bufb+16384u+swz(r,c),gA1+(size_t)r*D_+k0+c*8);}
      #pragma unroll
      for(int j=0;j<8;j++){int it=tid+256*j;u32 r=(u32)(it>>3),c=(u32)(it&7);
        cpa(bufb+OFF_W0+swz(r,c),gW0+(size_t)r*D_+k0+c*8);
        if(WLO) cpa(bufb+OFF_W1+swz(r,c),gW1+(size_t)r*D_+k0+c*8);}
      CPC(); CPW1();
    } else CPW0();
    __syncthreads();
    u32 ba=sb+(u32)(kc&1)*BUFSZ;
    #pragma unroll
    for(int kx=0;kx<4;kx++){
      int k16=(kx+(w&3))&3;               // warp-staggered K order
      u32 rA=(u32)(wm+(t&7)+((t>>3)&1)*8);
      u32 cA=(u32)(k16*2+(t>>4));
      u32 rB=(u32)(wn+(t&7)+((t>>4)<<3));
      u32 cB=(u32)(k16*2+((t>>3)&1));
      u32 bh[4][4],bl[4][4];
      #pragma unroll
      for(int nn=0;nn<4;nn++){
        ldsm4(bh[nn],ba+OFF_W0+swz(rB+(u32)nn*16u,cB));
        if(WLO) ldsm4(bl[nn],ba+OFF_W1+swz(rB+(u32)nn*16u,cB));
      }
      #pragma unroll
      for(int mt=0;mt<4;mt++){
        u32 aH[4],aL[4];
        ldsm4(aH,ba+swz(rA+(u32)mt*16u,cA));
        if(THREE) ldsm4(aL,ba+16384u+swz(rA+(u32)mt*16u,cA));
        #pragma unroll
        for(int nn=0;nn<4;nn++){
          mma16816(acc[mt][2*nn],aH,bh[nn][0],bh[nn][1]);
          mma16816(acc[mt][2*nn+1],aH,bh[nn][2],bh[nn][3]);
        }
        if(WLO){
          #pragma unroll
          for(int nn=0;nn<4;nn++){
            mma16816(acc[mt][2*nn],aH,bl[nn][0],bl[nn][1]);
            mma16816(acc[mt][2*nn+1],aH,bl[nn][2],bl[nn][3]);
          }
        }
        if(THREE){
          #pragma unroll
          for(int nn=0;nn<4;nn++){
            mma16816(acc[mt][2*nn],aL,bh[nn][0],bh[nn][1]);
            mma16816(acc[mt][2*nn+1],aL,bh[nn][2],bh[nn][3]);
          }
        }
      }
    }
  }
  #pragma unroll
  for(int mt=0;mt<4;mt++){
    int R0=bm+wm+mt*16+(t>>2);
    #pragma unroll
    for(int j=0;j<8;j++){
      int col=bn+wn+j*8+(t&3)*2;
      float c0=acc[mt][j][0],c1=acc[mt][j][1],c2=acc[mt][j][2],c3=acc[mt][j][3];
      if(Cf){
        float b0=bias[col],b1=bias[col+1];
        float2 v0; v0.x=c0+b0; v0.y=c1+b1;
        float2 v1; v1.x=c2+b0; v1.y=c3+b1;
        *(float2*)(Cf+(size_t)R0*D_+col)=v0;
        *(float2*)(Cf+(size_t)(R0+8)*D_+col)=v1;
      }else{
        __half h0,l0,h1,l1;
        spl(c0,h0,l0);spl(c1,h1,l1);
        *(u32*)(Ch+(size_t)R0*D_+col)=pkh(h0,h1);
        *(u32*)(Cl+(size_t)R0*D_+col)=pkh(l0,l1);
        spl(c2,h0,l0);spl(c3,h1,l1);
        *(u32*)(Ch+(size_t)(R0+8)*D_+col)=pkh(h0,h1);
        *(u32*)(Cl+(size_t)(R0+8)*D_+col)=pkh(l0,l1);
      }
    }
  }
}

// ---------------- HMMA attention (q=k=v), fixed-shift softmax, exact diag ----
// CTA: 64 q-rows, 128 thr. QK = Qh*Kh + exact fp32 diagonal; PV = P*Vh.
// Q fragments hoisted; S accumulator initialized to -SHIFT2 (no per-exp FADD);
// row-sums via ones-B MMA (no per-thread lsum FADDs, no shfl reduction).
__global__ __launch_bounds__(128,2)
void attn_mma(const __half* __restrict__ qh,const __half* __restrict__ ql,
              __half* __restrict__ oh){
  extern __shared__ char smraw[];
  u32 sb=(s2u(smraw)+1023)&~1023u;
  const int tid=threadIdx.x,t=tid&31,w=tid>>5;
  const int mi=w>>1,ni=w&1;
  const int qt=blockIdx.x,hb=blockIdx.y,b=hb>>4,h=hb&15;
  const size_t base=(size_t)b*S_*D_+(size_t)h*64;
  const int q0=qt*64;
  const int dkt=qt>>1;
  const int off=(qt&1)*64;
  const u32 LD=sb+8192;
  const u32 KB=sb+9216;
  const u32 ONE2=0x3C003C00u;          // fp16 {1,1}
  float* Ldp=(float*)(smraw+(LD-s2u(smraw)));
  // Q: combine h+l in fp32, scale by QS2, store fp16 (K-major SW)
  {
    const __half* gqh=qh+base+(size_t)q0*D_;
    const __half* gql=ql+base+(size_t)q0*D_;
    #pragma unroll
    for(int j=0;j<4;j++){int it=tid+128*j;u32 r=(u32)(it>>3),c=(u32)(it&7);
      uint4 vh4=*(const uint4*)(gqh+(size_t)r*D_+c*8);
      uint4 vl4=*(const uint4*)(gql+(size_t)r*D_+c*8);
      const __half* hv=(const __half*)&vh4; const __half* lv=(const __half*)&vl4;
      u32 wh[4];
      #pragma unroll
      for(int e=0;e<4;e++){
        float a0=(__half2float(hv[2*e])+__half2float(lv[2*e]))*QS2;
        float a1=(__half2float(hv[2*e+1])+__half2float(lv[2*e+1]))*QS2;
        wh[e]=pkf(a0,a1);
      }
      u32 d0=sb+swz(r,c);
      asm volatile("st.shared.v4.b32 [%0],{%1,%2,%3,%4};"::"r"(d0),"r"(wh[0]),"r"(wh[1]),"r"(wh[2]),"r"(wh[3]):"memory");
    }
  }
  // Exact diagonal
  {
    int r=tid>>1, hf=tid&1;
    const __half* ph=qh+base+(size_t)(q0+r)*D_+hf*32;
    const __half* pl2=ql+base+(size_t)(q0+r)*D_+hf*32;
    float acc2=0.f;
    #pragma unroll
    for(int c=0;c<4;c++){
      uint4 vh4=*(const uint4*)(ph+c*8);
      uint4 vl4=*(const uint4*)(pl2+c*8);
      const __half* hv=(const __half*)&vh4; const __half* lv=(const __half*)&vl4;
      #pragma unroll
      for(int e=0;e<8;e++){
        float v=__half2float(hv[e])+__half2float(lv[e]);
        acc2+=v*v;
      }
    }
    acc2+=__shfl_xor_sync(0xffffffffu,acc2,1);
    if(hf==0) Ldp[r]=acc2*QS2;
  }
  // prefetch K tile 0 (hi half only)
  {
    const __half* gpk=qh+base;
    #pragma unroll
    for(int j=0;j<8;j++){int it=tid+128*j;u32 r=(u32)(it>>3),c=(u32)(it&7);
      cpa(KB+swz(r,c),gpk+(size_t)r*D_+c*8);}
  }
  CPC();
  // hoist Q fragments
  __syncthreads();
  u32 qf[4][2][4];
  {
    u32 rA=(u32)(mi*32+(t&7)+((t>>3)&1)*8);
    #pragma unroll
    for(int k16=0;k16<4;k16++){
      u32 cA=(u32)(k16*2+(t>>4));
      ldsm4(qf[k16][0],sb+swz(rA,cA));
      ldsm4(qf[k16][1],sb+swz(rA+16,cA));
    }
  }
  float o[2][8][4]; float lsa[2][4];
  #pragma unroll
  for(int a=0;a<2;a++)for(int j=0;j<8;j++)for(int e=0;e<4;e++)o[a][j][e]=0.f;
  #pragma unroll
  for(int a=0;a<2;a++)for(int e=0;e<4;e++)lsa[a][e]=0.f;
  #pragma unroll 1
  for(int kt=0;kt<16;kt++){
    __syncthreads();
    if(kt<15){
      u32 st=(u32)((kt+1)&1);
      const __half* gpk=qh+base+(size_t)((kt+1)*128)*D_;
      #pragma unroll
      for(int j=0;j<8;j++){int it=tid+128*j;u32 r=(u32)(it>>3),c=(u32)(it&7);
        cpa(KB+st*16384+swz(r,c),gpk+(size_t)r*D_+c*8);}
      CPC(); CPW1();
    } else CPW0();
    __syncthreads();
    u32 kb=KB+(u32)(kt&1)*16384;
    float s[2][8][4];
    #pragma unroll
    for(int a=0;a<2;a++)for(int j=0;j<8;j++)for(int e=0;e<4;e++)s[a][j][e]=-SHIFT2;
    u32 rBb=(u32)(ni*64+(t&7)+((t>>4)<<3));
    #pragma unroll
    for(int k16=0;k16<4;k16++){
      u32 cB=(u32)(k16*2+((t>>3)&1));
      u32 bh[4][4];
      #pragma unroll
      for(int jj=0;jj<4;jj++) ldsm4(bh[jj],kb+swz(rBb+jj*16,cB));
      #pragma unroll
      for(int jj=0;jj<4;jj++)
        #pragma unroll
        for(int mt=0;mt<2;mt++){
          mma16816(s[mt][2*jj],qf[k16][mt],bh[jj][0],bh[jj][1]);
          mma16816(s[mt][2*jj+1],qf[k16][mt],bh[jj][2],bh[jj][3]);
        }
    }
    // exact diagonal patch (one kt per CTA), pre-shifted
    if(kt==dkt){
      #pragma unroll
      for(int mt=0;mt<2;mt++)
        #pragma unroll
        for(int j=0;j<8;j++)
          #pragma unroll
          for(int e=0;e<4;e++){
            int rl=mi*32+mt*16+(t>>2)+((e>>1)<<3);
            int cl=ni*64+j*8+(t&3)*2+(e&1);
            if(rl+off==cl) s[mt][j][e]=Ldp[rl]-SHIFT2;
          }
    }
    u32 pl[2][8][2];
    #pragma unroll
    for(int mt=0;mt<2;mt++)
      #pragma unroll
      for(int j=0;j<8;j++){
        float p0=ex2(s[mt][j][0]),p1=ex2(s[mt][j][1]);
        float p2=ex2(s[mt][j][2]),p3=ex2(s[mt][j][3]);
        pl[mt][j][0]=pkf(p0,p1); pl[mt][j][1]=pkf(p2,p3);
      }
    u32 rV0=(u32)(ni*64+(t&7)+((t>>3)&1)*8);
    #pragma unroll
    for(int kc=0;kc<4;kc++){
      u32 rV=rV0+kc*16;
      u32 af[2][4];
      #pragma unroll
      for(int mt=0;mt<2;mt++){
        af[mt][0]=pl[mt][2*kc][0]; af[mt][1]=pl[mt][2*kc][1];
        af[mt][2]=pl[mt][2*kc+1][0]; af[mt][3]=pl[mt][2*kc+1][1];
        // row-sum via ones-B MMA: lsa[mt] += P_rows . 1
        mma16816(lsa[mt],af[mt],ONE2,ONE2);
      }
      #pragma unroll
      for(int nn=0;nn<4;nn++){
        u32 cV=(u32)(nn*2+(t>>4));
        u32 vh[4];
        ldsm4t(vh,kb+swz(rV,cV));
        #pragma unroll
        for(int mt=0;mt<2;mt++){
          mma16816(o[mt][2*nn],af[mt],vh[0],vh[1]);
          mma16816(o[mt][2*nn+1],af[mt],vh[2],vh[3]);
        }
      }
    }
  }
  __syncthreads();
  // lsa[mt][0] = row sum for row (mi*32+mt*16+(t>>2)); lsa[mt][2] = +8 row.
  u32 Osm=KB, Lsm=sb;
  if(ni==1){
    #pragma unroll
    for(int mt=0;mt<2;mt++){
      int r0=mi*32+mt*16+(t>>2);
      #pragma unroll
      for(int j=0;j<8;j++){
        int c=j*8+(t&3)*2;
        asm volatile("st.shared.v2.f32 [%0],{%1,%2};"::"r"(Osm+(u32)((r0*64+c)*4)),"f"(o[mt][j][0]),"f"(o[mt][j][1]):"memory");
        asm volatile("st.shared.v2.f32 [%0],{%1,%2};"::"r"(Osm+(u32)(((r0+8)*64+c)*4)),"f"(o[mt][j][2]),"f"(o[mt][j][3]):"memory");
      }
      if((t&3)==0){
        asm volatile("st.shared.f32 [%0],%1;"::"r"(Lsm+(u32)(r0*4)),"f"(lsa[mt][0]):"memory");
        asm volatile("st.shared.f32 [%0],%1;"::"r"(Lsm+(u32)((r0+8)*4)),"f"(lsa[mt][2]):"memory");
      }
    }
  }
  __syncthreads();
  if(ni==0){
    #pragma unroll
    for(int mt=0;mt<2;mt++){
      int rloc=mi*32+mt*16+(t>>2);
      float lA,lB;
      asm volatile("ld.shared.f32 %0,[%1];":"=f"(lA):"r"(Lsm+(u32)(rloc*4)));
      asm volatile("ld.shared.f32 %0,[%1];":"=f"(lB):"r"(Lsm+(u32)((rloc+8)*4)));
      float iA=1.f/(lsa[mt][0]+lA), iB=1.f/(lsa[mt][2]+lB);
      size_t R0=base+(size_t)(q0+rloc)*D_;
      size_t R1=base+(size_t)(q0+rloc+8)*D_;
      #pragma unroll
      for(int j=0;j<8;j++){
        int c=j*8+(t&3)*2;
        float a0,a1,b0f,b1f;
        asm volatile("ld.shared.v2.f32 {%0,%1},[%2];":"=f"(a0),"=f"(a1):"r"(Osm+(u32)((rloc*64+c)*4)));
        asm volatile("ld.shared.v2.f32 {%0,%1},[%2];":"=f"(b0f),"=f"(b1f):"r"(Osm+(u32)(((rloc+8)*64+c)*4)));
        float v0=(o[mt][j][0]+a0)*iA, v1=(o[mt][j][1]+a1)*iA;
        float v2=(o[mt][j][2]+b0f)*iB, v3=(o[mt][j][3]+b1f)*iB;
        *(u32*)(oh+R0+c)=pkf(v0,v1);
        *(u32*)(oh+R1+c)=pkf(v2,v3);
      }
    }
  }
}

// ---------------------------------------------------------------------------
extern "C" void kernel_launch(void* const* d_in, const int* in_sizes, int n_in,
                              void* d_out, int out_size) {
    const float* x=(const float*)d_in[0];
    const float* w_qkv=(const float*)d_in[1];
    const float* w_out=(const float*)d_in[2];
    const float* b_out=(const float*)d_in[3];
    float* out=(float*)d_out;

    __half *xh,*qh,*ql,*ah,*wqh,*wql,*woh,*wol;
    cudaGetSymbolAddress((void**)&xh,g_xh);
    cudaGetSymbolAddress((void**)&qh,g_qh);   cudaGetSymbolAddress((void**)&ql,g_ql);
    cudaGetSymbolAddress((void**)&ah,g_ah);
    cudaGetSymbolAddress((void**)&wqh,g_wqh); cudaGetSymbolAddress((void**)&wql,g_wql);
    cudaGetSymbolAddress((void**)&woh,g_woh); cudaGetSymbolAddress((void**)&wol,g_wol);

    const int SMG2=163840+1024, SMG1=98304+1024, SMA=9216+32768+1024;
    cudaFuncSetAttribute(gemm_mma<2>, cudaFuncAttributeMaxDynamicSharedMemorySize, SMG2);
    cudaFuncSetAttribute(gemm_mma<1>, cudaFuncAttributeMaxDynamicSharedMemorySize, SMG1);
    cudaFuncSetAttribute(attn_mma, cudaFuncAttributeMaxDynamicSharedMemorySize, SMA);

    split_h<<<(NT*D_)/1024,256>>>(x,xh,NT*D_);
    split_k<<<(D_*D_)/1024,256>>>(w_qkv,wqh,wql,D_*D_);
    split_k<<<(D_*D_)/1024,256>>>(w_out,woh,wol,D_*D_);

    dim3 g1(D_/256, NT/128);             // (4, 64) = 256 CTAs
    gemm_mma<2><<<g1,256,SMG2>>>(xh,nullptr,wqh,wql,nullptr,qh,ql,nullptr);

    dim3 g2(S_/64, 64);                  // (32, 64)
    attn_mma<<<g2,128,SMA>>>(qh,ql,ah);

    gemm_mma<1><<<g1,256,SMG1>>>(ah,nullptr,woh,nullptr,b_out,nullptr,nullptr,out);
}